// round 6
// baseline (speedup 1.0000x reference)
#include <cuda_runtime.h>
#include <cuda_bf16.h>
#include <math.h>
#include <stdint.h>

// ===========================================================================
// bf16x3 split GEMM via legacy mma.sync (compute_103-safe: no tcgen05).
// C[M,N] = A[M,K] @ B[N,K]^T with A,B pre-split into (bf16 hi, bf16 lo).
// acc = Ah*Bh + Ah*Bl + Al*Bh  (fp32 accumulators).
// R5: 128x256x32 tile, 4-stage cp.async, 1 CTA/SM, 64x64 warp tiles.
// ===========================================================================

#define TILE_A  8192             // 128x32 bf16 (A hi or lo)
#define TILE_BT 16384            // 256x32 bf16 (B hi or lo)
#define STAGE_B 49152            // Ah + Al + Bh + Bl
#define SMEM_B3 196608           // 4 stages

__device__ __forceinline__ uint32_t smem_u32(const void* p) {
    uint32_t a;
    asm("{ .reg .u64 t; cvta.to.shared.u64 t, %1; cvt.u32.u64 %0, t; }" : "=r"(a) : "l"(p));
    return a;
}
__device__ __forceinline__ void cp16(uint32_t s, const void* g) {
    asm volatile("cp.async.cg.shared.global [%0], [%1], 16;" :: "r"(s), "l"(g));
}
#define CP_COMMIT() asm volatile("cp.async.commit_group;" ::: "memory")
#define CP_WAIT2()  asm volatile("cp.async.wait_group 2;" ::: "memory")
#define LDSM4(R, a) \
    asm volatile("ldmatrix.sync.aligned.m8n8.x4.shared.b16 {%0,%1,%2,%3}, [%4];" \
        : "=r"((R)[0]), "=r"((R)[1]), "=r"((R)[2]), "=r"((R)[3]) : "r"(a))

__device__ __forceinline__ void mma_bf16(float* c, const uint32_t* a, uint32_t b0, uint32_t b1) {
    asm volatile(
        "mma.sync.aligned.m16n8k16.row.col.f32.bf16.bf16.f32 "
        "{%0,%1,%2,%3}, {%4,%5,%6,%7}, {%8,%9}, {%0,%1,%2,%3};"
        : "+f"(c[0]), "+f"(c[1]), "+f"(c[2]), "+f"(c[3])
        : "r"(a[0]), "r"(a[1]), "r"(a[2]), "r"(a[3]), "r"(b0), "r"(b1));
}

// 16B-granular XOR swizzle within a [rows x 32] bf16 tile (64B rows).
__device__ __forceinline__ uint32_t sw(int row, int col16) {
    return (uint32_t)(row * 64 + ((col16 ^ ((row >> 1) & 3)) << 4));
}

// load one pipeline stage: A 128x32 (hi,lo) + B 256x32 (hi,lo)
__device__ __forceinline__ void ld_stage(
    uint32_t sb, int buf, int t,
    const __nv_bfloat16* __restrict__ Ah, const __nv_bfloat16* __restrict__ Al,
    const __nv_bfloat16* __restrict__ Bh, const __nv_bfloat16* __restrict__ Bl,
    int bm, int bn, int K, int tid)
{
    const int k0 = t * 32;
    const uint32_t stb = sb + (uint32_t)buf * STAGE_B;
#pragma unroll
    for (int i = 0; i < 2; i++) {
        const int c = tid + i * 256;
        const int row = c >> 2, col16 = c & 3;
        const size_t gA = (size_t)(bm + row) * K + k0 + col16 * 8;
        const uint32_t so = stb + sw(row, col16);
        cp16(so,          Ah + gA);
        cp16(so + TILE_A, Al + gA);
    }
#pragma unroll
    for (int i = 0; i < 4; i++) {
        const int c = tid + i * 256;
        const int row = c >> 2, col16 = c & 3;
        const size_t gB = (size_t)(bn + row) * K + k0 + col16 * 8;
        const uint32_t so = stb + 2 * TILE_A + sw(row, col16);
        cp16(so,           Bh + gB);
        cp16(so + TILE_BT, Bl + gB);
    }
}

// EPI 0: split-write (Ch,Cl bf16).  EPI 1: fp32 write Cf.
// EPI 2: v = OTH * silu(acc), split-write.
template <int EPI>
__global__ __launch_bounds__(256, 1) void gemm_b3(
    const __nv_bfloat16* __restrict__ Ah, const __nv_bfloat16* __restrict__ Al,
    const __nv_bfloat16* __restrict__ Bh, const __nv_bfloat16* __restrict__ Bl,
    float* __restrict__ Cf, __nv_bfloat16* __restrict__ Ch, __nv_bfloat16* __restrict__ Cl,
    const float* __restrict__ OTH, int M, int N, int K)
{
    extern __shared__ char smem[];
    const uint32_t sb = smem_u32(smem);
    const int tid = threadIdx.x;

    // ---- L2-friendly CTA rasterization (GROUP_M = 16) ----
    const int gn = gridDim.x, gm = gridDim.y;
    const int bid = blockIdx.y * gn + blockIdx.x;
    const int npg = 16 * gn;
    const int gid = bid / npg;
    const int fm = gid * 16;
    const int gs = (gm - fm < 16) ? (gm - fm) : 16;
    const int bm = (fm + (bid % gs)) * 128;
    const int bn = ((bid % npg) / gs) * 256;

    const int w = tid >> 5, lane = tid & 31;
    const int wm = (w >> 2) * 64, wn = (w & 3) * 64;
    const int jj = lane >> 3, rr = lane & 7;
    const int aR = (jj & 1) * 8 + rr, aC16 = jj >> 1;   // A: (m0k0)(m8k0)(m0k8)(m8k8)
    const int bR = (jj >> 1) * 8 + rr, bC16 = jj & 1;   // B: (n0k0)(n0k8)(n8k0)(n8k8)

    float c[4][8][4];
#pragma unroll
    for (int mi = 0; mi < 4; mi++)
#pragma unroll
        for (int ni = 0; ni < 8; ni++)
#pragma unroll
            for (int q = 0; q < 4; q++) c[mi][ni][q] = 0.0f;

    const int nst = K / 32;
    ld_stage(sb, 0, 0, Ah, Al, Bh, Bl, bm, bn, K, tid); CP_COMMIT();
    ld_stage(sb, 1, 1, Ah, Al, Bh, Bl, bm, bn, K, tid); CP_COMMIT();
    ld_stage(sb, 2, 2, Ah, Al, Bh, Bl, bm, bn, K, tid); CP_COMMIT();

    for (int t = 0; t < nst; t++) {
        CP_WAIT2();
        __syncthreads();
        if (t + 3 < nst)
            ld_stage(sb, (t + 3) & 3, t + 3, Ah, Al, Bh, Bl, bm, bn, K, tid);
        CP_COMMIT();

        const uint32_t stb = sb + (uint32_t)((t & 3) * STAGE_B);
#pragma unroll
        for (int ks = 0; ks < 2; ks++) {
            uint32_t af[4][4], bhf[4][4], blf[4][4];
            // B-hi / B-lo frags (n = 64 -> 4 x n16)
#pragma unroll
            for (int np = 0; np < 4; np++) {
                const uint32_t bd = stb + 2 * TILE_A + sw(wn + np * 16 + bR, ks * 2 + bC16);
                LDSM4(bhf[np], bd);
                LDSM4(blf[np], bd + TILE_BT);
            }
            // A-hi frags
#pragma unroll
            for (int mi = 0; mi < 4; mi++)
                LDSM4(af[mi], stb + sw(wm + mi * 16 + aR, ks * 2 + aC16));
            // hh + hl
#pragma unroll
            for (int mi = 0; mi < 4; mi++)
#pragma unroll
                for (int ni = 0; ni < 8; ni++) {
                    const int p = ni >> 1, q = (ni & 1) * 2;
                    mma_bf16(c[mi][ni], af[mi], bhf[p][q], bhf[p][q + 1]);
                    mma_bf16(c[mi][ni], af[mi], blf[p][q], blf[p][q + 1]);
                }
            // A-lo frags overwrite A-hi (reduced liveness)
#pragma unroll
            for (int mi = 0; mi < 4; mi++)
                LDSM4(af[mi], stb + TILE_A + sw(wm + mi * 16 + aR, ks * 2 + aC16));
            // lh
#pragma unroll
            for (int mi = 0; mi < 4; mi++)
#pragma unroll
                for (int ni = 0; ni < 8; ni++) {
                    const int p = ni >> 1, q = (ni & 1) * 2;
                    mma_bf16(c[mi][ni], af[mi], bhf[p][q], bhf[p][q + 1]);
                }
        }
    }

    // ---- epilogue ----
#pragma unroll
    for (int mi = 0; mi < 4; mi++)
#pragma unroll
        for (int ni = 0; ni < 8; ni++) {
            const int r0 = bm + wm + mi * 16 + (lane >> 2);
            const int col = bn + wn + ni * 8 + (lane & 3) * 2;
            const size_t o0 = (size_t)r0 * N + col;
            const size_t o1 = (size_t)(r0 + 8) * N + col;
            float v0 = c[mi][ni][0], v1 = c[mi][ni][1];
            float v2 = c[mi][ni][2], v3 = c[mi][ni][3];
            if (EPI == 2) {
                const float2 u0 = *(const float2*)(OTH + o0);
                const float2 u1 = *(const float2*)(OTH + o1);
                v0 = u0.x * (v0 / (1.0f + expf(-v0)));
                v1 = u0.y * (v1 / (1.0f + expf(-v1)));
                v2 = u1.x * (v2 / (1.0f + expf(-v2)));
                v3 = u1.y * (v3 / (1.0f + expf(-v3)));
            }
            if (EPI == 1) {
                *(float2*)(Cf + o0) = make_float2(v0, v1);
                *(float2*)(Cf + o1) = make_float2(v2, v3);
            } else {
                __nv_bfloat162 hh, ll;
                hh.x = __float2bfloat16(v0); hh.y = __float2bfloat16(v1);
                ll.x = __float2bfloat16(v0 - __bfloat162float(hh.x));
                ll.y = __float2bfloat16(v1 - __bfloat162float(hh.y));
                *(__nv_bfloat162*)(Ch + o0) = hh;
                *(__nv_bfloat162*)(Cl + o0) = ll;
                hh.x = __float2bfloat16(v2); hh.y = __float2bfloat16(v3);
                ll.x = __float2bfloat16(v2 - __bfloat162float(hh.x));
                ll.y = __float2bfloat16(v3 - __bfloat162float(hh.y));
                *(__nv_bfloat162*)(Ch + o1) = hh;
                *(__nv_bfloat162*)(Cl + o1) = ll;
            }
        }
}

// ===========================================================================
// scratch (static; no allocations). bf16 slab 768M elems + fp32 C1.
// ===========================================================================
#define MDE 16777216ll
#define FFE 67108864ll
__device__ __nv_bfloat16 g_bf[805306368];
__device__ float g_c1[67108864];

// ---- pre-pass: fp32 -> (bf16 hi, bf16 lo) ----
struct bf4 { __nv_bfloat162 a, b; };
__global__ void split_k(const float4* __restrict__ in, bf4* __restrict__ hi,
                        bf4* __restrict__ lo, int n4) {
    for (int i = blockIdx.x * blockDim.x + threadIdx.x; i < n4; i += gridDim.x * blockDim.x) {
        const float4 v = in[i];
        bf4 H, L;
        H.a.x = __float2bfloat16(v.x); H.a.y = __float2bfloat16(v.y);
        H.b.x = __float2bfloat16(v.z); H.b.y = __float2bfloat16(v.w);
        L.a.x = __float2bfloat16(v.x - __bfloat162float(H.a.x));
        L.a.y = __float2bfloat16(v.y - __bfloat162float(H.a.y));
        L.b.x = __float2bfloat16(v.z - __bfloat162float(H.b.x));
        L.b.y = __float2bfloat16(v.w - __bfloat162float(H.b.y));
        hi[i] = H; lo[i] = L;
    }
}
// transpose + split: out_{hi,lo}[n*F+k] = split(in[k*F+n])
__global__ void tsplit_k(const float* __restrict__ in, __nv_bfloat16* __restrict__ hi,
                         __nv_bfloat16* __restrict__ lo, int F) {
    __shared__ float t[32][33];
    const int c0 = blockIdx.x * 32, r0 = blockIdx.y * 32;
#pragma unroll
    for (int i = 0; i < 32; i += 8)
        t[threadIdx.y + i][threadIdx.x] = in[(size_t)(r0 + threadIdx.y + i) * F + c0 + threadIdx.x];
    __syncthreads();
#pragma unroll
    for (int i = 0; i < 32; i += 8) {
        const float v = t[threadIdx.x][threadIdx.y + i];
        const __nv_bfloat16 h = __float2bfloat16(v);
        const size_t o = (size_t)(c0 + threadIdx.y + i) * F + r0 + threadIdx.x;
        hi[o] = h;
        lo[o] = __float2bfloat16(v - __bfloat162float(h));
    }
}

// ===========================================================================
static void rung(int epi,
                 const __nv_bfloat16* Ah, const __nv_bfloat16* Al,
                 const __nv_bfloat16* Bh, const __nv_bfloat16* Bl,
                 float* Cf, __nv_bfloat16* Ch, __nv_bfloat16* Cl,
                 const float* OTH, int M, int N, int K)
{
    const dim3 g(N / 256, M / 128), b(256);
    if (epi == 0) {
        cudaFuncSetAttribute(gemm_b3<0>, cudaFuncAttributeMaxDynamicSharedMemorySize, SMEM_B3);
        gemm_b3<0><<<g, b, SMEM_B3>>>(Ah, Al, Bh, Bl, Cf, Ch, Cl, OTH, M, N, K);
    } else if (epi == 1) {
        cudaFuncSetAttribute(gemm_b3<1>, cudaFuncAttributeMaxDynamicSharedMemorySize, SMEM_B3);
        gemm_b3<1><<<g, b, SMEM_B3>>>(Ah, Al, Bh, Bl, Cf, Ch, Cl, OTH, M, N, K);
    } else {
        cudaFuncSetAttribute(gemm_b3<2>, cudaFuncAttributeMaxDynamicSharedMemorySize, SMEM_B3);
        gemm_b3<2><<<g, b, SMEM_B3>>>(Ah, Al, Bh, Bl, Cf, Ch, Cl, OTH, M, N, K);
    }
}

extern "C" void kernel_launch(void* const* d_in, const int* in_sizes, int n_in,
                              void* d_out, int out_size)
{
    const float* x  = (const float*)d_in[0];
    const float* wu = (const float*)d_in[1];
    const float* wg = (const float*)d_in[2];
    const float* wd = (const float*)d_in[3];
    const float* h1 = (const float*)d_in[4];
    const float* h2 = (const float*)d_in[5];
    const float* h3 = (const float*)d_in[6];

    int F = 1;
    while ((long long)(F + 1) * (F + 1) <= (long long)in_sizes[4]) F++;
    const int D = in_sizes[1] / F;
    const int M = in_sizes[0] / D;

    __nv_bfloat16* bb;
    float* C1;
    cudaGetSymbolAddress((void**)&bb, g_bf);
    cudaGetSymbolAddress((void**)&C1, g_c1);

    __nv_bfloat16 *xh = bb,            *xl = bb + MDE;
    __nv_bfloat16 *wuh = bb + 2 * MDE, *wul = bb + 3 * MDE;
    __nv_bfloat16 *wgh = bb + 4 * MDE, *wgl = bb + 5 * MDE;
    __nv_bfloat16 *wdh = bb + 6 * MDE, *wdl = bb + 7 * MDE;
    __nv_bfloat16* hb = bb + 8 * MDE;
    __nv_bfloat16 *h1h = hb,           *h1l = hb + FFE;
    __nv_bfloat16 *h2h = hb + 2 * FFE, *h2l = hb + 3 * FFE;
    __nv_bfloat16 *h3h = hb + 4 * FFE, *h3l = hb + 5 * FFE;
    __nv_bfloat16 *Uh = hb + 6 * FFE,  *Ul = hb + 7 * FFE;
    __nv_bfloat16 *Gh = hb + 8 * FFE,  *Gl = hb + 9 * FFE;

    const int nMD4 = (M * D) / 4, nFD4 = (F * D) / 4;
    split_k<<<2048, 256>>>((const float4*)x,  (bf4*)xh,  (bf4*)xl,  nMD4);
    split_k<<<2048, 256>>>((const float4*)wu, (bf4*)wuh, (bf4*)wul, nFD4);
    split_k<<<2048, 256>>>((const float4*)wg, (bf4*)wgh, (bf4*)wgl, nFD4);
    split_k<<<2048, 256>>>((const float4*)wd, (bf4*)wdh, (bf4*)wdl, nFD4);
    const dim3 tg(F / 32, F / 32), tb(32, 8);
    tsplit_k<<<tg, tb>>>(h1, h1h, h1l, F);
    tsplit_k<<<tg, tb>>>(h2, h2h, h2l, F);
    tsplit_k<<<tg, tb>>>(h3, h3h, h3l, F);

    // 1) up   = x @ w_up^T            -> split U
    rung(0, xh, xl, wuh, wul, nullptr, Uh, Ul, nullptr, M, F, D);
    // 2) gate = x @ w_gate^T          -> split G
    rung(0, xh, xl, wgh, wgl, nullptr, Gh, Gl, nullptr, M, F, D);
    // 3) up2  = U @ h_up_T            -> C1 (fp32)
    rung(1, Uh, Ul, h1h, h1l, C1, nullptr, nullptr, nullptr, M, F, F);
    // 4) gated = C1 * silu(G @ h_gate_T) -> split U (reuse)
    rung(2, Gh, Gl, h2h, h2l, nullptr, Uh, Ul, C1, M, F, F);
    // 5) g3   = gated @ h_down        -> split G (reuse)
    rung(0, Uh, Ul, h3h, h3l, nullptr, Gh, Gl, nullptr, M, F, F);
    // 6) out  = g3 @ w_down^T         -> d_out (fp32)
    rung(1, Gh, Gl, wdh, wdl, (float*)d_out, nullptr, nullptr, nullptr, M, D, F);
}

// round 7
// speedup vs baseline: 1.2840x; 1.2840x over previous
#include <cuda_runtime.h>
#include <cuda.h>
#include <cuda_bf16.h>
#include <math.h>
#include <stdint.h>

// ===========================================================================
// bf16x3 split GEMM via legacy mma.sync + TMA loads (compute_103-safe).
// C[M,N] = A[M,K] @ B[N,K]^T with A,B pre-split into (bf16 hi, bf16 lo).
// acc = Ah*Bh + Ah*Bl + Al*Bh  (fp32 accumulators).
// R6: R4 tile (128x128x32, 2 CTA/SM) with cp.async -> TMA (SWIZZLE_64B ==
// our 16B XOR swizzle), 3-stage mbarrier ring. Removes ~4K LDGSTS issue
// slots per SM-stage-pair that capped R4 at ~85% of HMMA peak.
// ===========================================================================

#define TILE_B 8192              // one 128x32 bf16 tile in smem (bytes)
#define STAGE_B 32768            // 4 tiles (Ah,Al,Bh,Bl)
#define SMEM_TOT (1024 + 1024 + 3 * STAGE_B)   // align pad + bars + 3 stages

__device__ __forceinline__ uint32_t smem_u32(const void* p) {
    uint32_t a;
    asm("{ .reg .u64 t; cvta.to.shared.u64 t, %1; cvt.u32.u64 %0, t; }" : "=r"(a) : "l"(p));
    return a;
}
#define MBARRIER_INIT(a, c) \
    asm volatile("mbarrier.init.shared.b64 [%0], %1;" :: "r"((uint32_t)(a)), "r"((uint32_t)(c)) : "memory")
#define MBARRIER_EXPECT_TX(a, b) \
    asm volatile("mbarrier.arrive.expect_tx.shared.b64 _, [%0], %1;" :: "r"((uint32_t)(a)), "r"((uint32_t)(b)) : "memory")
#define MBARRIER_WAIT_PARITY(a, p) do { \
    uint32_t _m = (uint32_t)(a), _p = (uint32_t)(p), _d; \
    asm volatile("{\n\t.reg .pred q;\n\t" \
        "mbarrier.try_wait.parity.acquire.cta.shared::cta.b64 q, [%1], %2;\n\t" \
        "selp.b32 %0, 1, 0, q;\n\t}" : "=r"(_d) : "r"(_m), "r"(_p) : "memory"); \
    if (!_d) { \
        asm volatile("{\n\t.reg .pred Q;\n\t" \
            "WL_%=:\n\t" \
            "mbarrier.try_wait.parity.acquire.cta.shared::cta.b64 Q, [%0], %1, 0x989680;\n\t" \
            "@Q bra.uni WD_%=;\n\t" \
            "bra.uni WL_%=;\n\t" \
            "WD_%=:\n\t}" :: "r"(_m), "r"(_p) : "memory"); \
    } \
} while (0)
#define TMA_LOAD_3D(sa, tm, cx, cy, cz, mb) \
    asm volatile("cp.async.bulk.tensor.3d.shared::cta.global.tile.mbarrier::complete_tx::bytes " \
        "[%0], [%1, {%2, %3, %4}], [%5];" \
        :: "r"((uint32_t)(sa)), "l"(tm), "r"((int32_t)(cx)), "r"((int32_t)(cy)), \
           "r"((int32_t)(cz)), "r"((uint32_t)(mb)) : "memory")
#define LDSM4(R, a) \
    asm volatile("ldmatrix.sync.aligned.m8n8.x4.shared.b16 {%0,%1,%2,%3}, [%4];" \
        : "=r"((R)[0]), "=r"((R)[1]), "=r"((R)[2]), "=r"((R)[3]) : "r"(a))

__device__ __forceinline__ void mma_bf16(float* c, const uint32_t* a, uint32_t b0, uint32_t b1) {
    asm volatile(
        "mma.sync.aligned.m16n8k16.row.col.f32.bf16.bf16.f32 "
        "{%0,%1,%2,%3}, {%4,%5,%6,%7}, {%8,%9}, {%0,%1,%2,%3};"
        : "+f"(c[0]), "+f"(c[1]), "+f"(c[2]), "+f"(c[3])
        : "r"(a[0]), "r"(a[1]), "r"(a[2]), "r"(a[3]), "r"(b0), "r"(b1));
}

// 16B-granular XOR swizzle within a [rows x 32] bf16 tile (64B rows).
// Identical to TMA CU_TENSOR_MAP_SWIZZLE_64B layout for 64B-wide boxes.
__device__ __forceinline__ uint32_t sw(int row, int col16) {
    return (uint32_t)(row * 64 + ((col16 ^ ((row >> 1) & 3)) << 4));
}

// EPI 0: split-write (Ch,Cl bf16).  EPI 1: fp32 write Cf.
// EPI 2: v = OTH * silu(acc), split-write.
template <int EPI>
__global__ __launch_bounds__(256, 2) void gemm_b3(
    const __grid_constant__ CUtensorMap tAh, const __grid_constant__ CUtensorMap tAl,
    const __grid_constant__ CUtensorMap tBh, const __grid_constant__ CUtensorMap tBl,
    float* __restrict__ Cf, __nv_bfloat16* __restrict__ Ch, __nv_bfloat16* __restrict__ Cl,
    const float* __restrict__ OTH, int M, int N, int K)
{
    extern __shared__ char smem[];
    const uint32_t sb0 = smem_u32(smem);
    const uint32_t sb = (sb0 + 1023) & ~1023u;   // 1KB-align for TMA swizzle
    const int tid = threadIdx.x;

    // ---- L2-friendly CTA rasterization (GROUP_M = 16) ----
    const int gn = gridDim.x, gm = gridDim.y;
    const int bid = blockIdx.y * gn + blockIdx.x;
    const int npg = 16 * gn;
    const int gid = bid / npg;
    const int fm = gid * 16;
    const int gs = (gm - fm < 16) ? (gm - fm) : 16;
    const int bm = (fm + (bid % gs)) * 128;
    const int bn = ((bid % npg) / gs) * 128;

    const int w = tid >> 5, lane = tid & 31;
    const int wm = (w >> 2) * 64, wn = (w & 3) * 32;
    const int jj = lane >> 3, rr = lane & 7;
    const int aR = (jj & 1) * 8 + rr, aC16 = jj >> 1;   // A: (m0k0)(m8k0)(m0k8)(m8k8)
    const int bR = (jj >> 1) * 8 + rr, bC16 = jj & 1;   // B: (n0k0)(n0k8)(n8k0)(n8k8)

    const uint32_t bars = sb;                 // 3 x 8B mbarriers
    const uint32_t stg0 = sb + 1024;          // 3 x 32KB stages

    if (tid == 0) {
        MBARRIER_INIT(bars + 0, 1);
        MBARRIER_INIT(bars + 8, 1);
        MBARRIER_INIT(bars + 16, 1);
    }
    __syncthreads();

    const int nst = K / 32;

    // prologue: issue stages 0..2
    if (tid == 0) {
#pragma unroll
        for (int s = 0; s < 3; s++) {
            const uint32_t bar = bars + s * 8;
            const uint32_t stb = stg0 + s * STAGE_B;
            const int k0 = s * 32;
            MBARRIER_EXPECT_TX(bar, STAGE_B);
            TMA_LOAD_3D(stb,              &tAh, k0, bm, 0, bar);
            TMA_LOAD_3D(stb + TILE_B,     &tAl, k0, bm, 0, bar);
            TMA_LOAD_3D(stb + 2 * TILE_B, &tBh, k0, bn, 0, bar);
            TMA_LOAD_3D(stb + 3 * TILE_B, &tBl, k0, bn, 0, bar);
        }
    }

    float c[4][4][4];
#pragma unroll
    for (int mi = 0; mi < 4; mi++)
#pragma unroll
        for (int ni = 0; ni < 4; ni++)
#pragma unroll
            for (int q = 0; q < 4; q++) c[mi][ni][q] = 0.0f;

    for (int t = 0; t < nst; t++) {
        const int buf = t % 3;
        MBARRIER_WAIT_PARITY(bars + buf * 8, (t / 3) & 1);

        const uint32_t stb = stg0 + (uint32_t)buf * STAGE_B;
#pragma unroll
        for (int ks = 0; ks < 2; ks++) {
            uint32_t af[4][4], bhf[2][4], blf[2][4];
            // A-hi frags
#pragma unroll
            for (int mi = 0; mi < 4; mi++)
                LDSM4(af[mi], stb + sw(wm + mi * 16 + aR, ks * 2 + aC16));
            // B-hi / B-lo frags
#pragma unroll
            for (int np = 0; np < 2; np++) {
                const uint32_t bd = stb + 2 * TILE_B + sw(wn + np * 16 + bR, ks * 2 + bC16);
                LDSM4(bhf[np], bd);
                LDSM4(blf[np], bd + TILE_B);
            }
            // hh + hl
#pragma unroll
            for (int mi = 0; mi < 4; mi++)
#pragma unroll
                for (int ni = 0; ni < 4; ni++) {
                    const int p = ni >> 1, q = (ni & 1) * 2;
                    mma_bf16(c[mi][ni], af[mi], bhf[p][q], bhf[p][q + 1]);
                    mma_bf16(c[mi][ni], af[mi], blf[p][q], blf[p][q + 1]);
                }
            // A-lo frags overwrite A-hi (reduced liveness)
#pragma unroll
            for (int mi = 0; mi < 4; mi++)
                LDSM4(af[mi], stb + TILE_B + sw(wm + mi * 16 + aR, ks * 2 + aC16));
            // lh
#pragma unroll
            for (int mi = 0; mi < 4; mi++)
#pragma unroll
                for (int ni = 0; ni < 4; ni++) {
                    const int p = ni >> 1, q = (ni & 1) * 2;
                    mma_bf16(c[mi][ni], af[mi], bhf[p][q], bhf[p][q + 1]);
                }
        }

        __syncthreads();   // all warps done reading buf before refill
        if (t + 3 < nst && tid == 0) {
            const uint32_t bar = bars + buf * 8;
            const int k0 = (t + 3) * 32;
            MBARRIER_EXPECT_TX(bar, STAGE_B);
            TMA_LOAD_3D(stb,              &tAh, k0, bm, 0, bar);
            TMA_LOAD_3D(stb + TILE_B,     &tAl, k0, bm, 0, bar);
            TMA_LOAD_3D(stb + 2 * TILE_B, &tBh, k0, bn, 0, bar);
            TMA_LOAD_3D(stb + 3 * TILE_B, &tBl, k0, bn, 0, bar);
        }
    }

    // ---- epilogue ----
#pragma unroll
    for (int mi = 0; mi < 4; mi++)
#pragma unroll
        for (int ni = 0; ni < 4; ni++) {
            const int r0 = bm + wm + mi * 16 + (lane >> 2);
            const int col = bn + wn + ni * 8 + (lane & 3) * 2;
            const size_t o0 = (size_t)r0 * N + col;
            const size_t o1 = (size_t)(r0 + 8) * N + col;
            float v0 = c[mi][ni][0], v1 = c[mi][ni][1];
            float v2 = c[mi][ni][2], v3 = c[mi][ni][3];
            if (EPI == 2) {
                const float2 u0 = *(const float2*)(OTH + o0);
                const float2 u1 = *(const float2*)(OTH + o1);
                v0 = u0.x * (v0 / (1.0f + expf(-v0)));
                v1 = u0.y * (v1 / (1.0f + expf(-v1)));
                v2 = u1.x * (v2 / (1.0f + expf(-v2)));
                v3 = u1.y * (v3 / (1.0f + expf(-v3)));
            }
            if (EPI == 1) {
                *(float2*)(Cf + o0) = make_float2(v0, v1);
                *(float2*)(Cf + o1) = make_float2(v2, v3);
            } else {
                __nv_bfloat162 hh, ll;
                hh.x = __float2bfloat16(v0); hh.y = __float2bfloat16(v1);
                ll.x = __float2bfloat16(v0 - __bfloat162float(hh.x));
                ll.y = __float2bfloat16(v1 - __bfloat162float(hh.y));
                *(__nv_bfloat162*)(Ch + o0) = hh;
                *(__nv_bfloat162*)(Cl + o0) = ll;
                hh.x = __float2bfloat16(v2); hh.y = __float2bfloat16(v3);
                ll.x = __float2bfloat16(v2 - __bfloat162float(hh.x));
                ll.y = __float2bfloat16(v3 - __bfloat162float(hh.y));
                *(__nv_bfloat162*)(Ch + o1) = hh;
                *(__nv_bfloat162*)(Cl + o1) = ll;
            }
        }
}

// ===========================================================================
// scratch (static; no allocations). bf16 slab 768M elems + fp32 C1.
// ===========================================================================
#define MDE 16777216ll
#define FFE 67108864ll
__device__ __nv_bfloat16 g_bf[805306368];
__device__ float g_c1[67108864];

// ---- pre-pass: fp32 -> (bf16 hi, bf16 lo) ----
struct bf4 { __nv_bfloat162 a, b; };
__global__ void split_k(const float4* __restrict__ in, bf4* __restrict__ hi,
                        bf4* __restrict__ lo, int n4) {
    for (int i = blockIdx.x * blockDim.x + threadIdx.x; i < n4; i += gridDim.x * blockDim.x) {
        const float4 v = in[i];
        bf4 H, L;
        H.a.x = __float2bfloat16(v.x); H.a.y = __float2bfloat16(v.y);
        H.b.x = __float2bfloat16(v.z); H.b.y = __float2bfloat16(v.w);
        L.a.x = __float2bfloat16(v.x - __bfloat162float(H.a.x));
        L.a.y = __float2bfloat16(v.y - __bfloat162float(H.a.y));
        L.b.x = __float2bfloat16(v.z - __bfloat162float(H.b.x));
        L.b.y = __float2bfloat16(v.w - __bfloat162float(H.b.y));
        hi[i] = H; lo[i] = L;
    }
}
// transpose + split: out_{hi,lo}[n*F+k] = split(in[k*F+n])
__global__ void tsplit_k(const float* __restrict__ in, __nv_bfloat16* __restrict__ hi,
                         __nv_bfloat16* __restrict__ lo, int F) {
    __shared__ float t[32][33];
    const int c0 = blockIdx.x * 32, r0 = blockIdx.y * 32;
#pragma unroll
    for (int i = 0; i < 32; i += 8)
        t[threadIdx.y + i][threadIdx.x] = in[(size_t)(r0 + threadIdx.y + i) * F + c0 + threadIdx.x];
    __syncthreads();
#pragma unroll
    for (int i = 0; i < 32; i += 8) {
        const float v = t[threadIdx.x][threadIdx.y + i];
        const __nv_bfloat16 h = __float2bfloat16(v);
        const size_t o = (size_t)(c0 + threadIdx.y + i) * F + r0 + threadIdx.x;
        hi[o] = h;
        lo[o] = __float2bfloat16(v - __bfloat162float(h));
    }
}

// ===========================================================================
typedef CUresult (*PFN_enc)(CUtensorMap*, CUtensorMapDataType, cuuint32_t, void*,
                            const cuuint64_t*, const cuuint64_t*, const cuuint32_t*,
                            const cuuint32_t*, CUtensorMapInterleave, CUtensorMapSwizzle,
                            CUtensorMapL2promotion, CUtensorMapFloatOOBfill);

static void enc_map(PFN_enc fn, CUtensorMap* m, const __nv_bfloat16* p, int K, int rows) {
    cuuint64_t dims[3] = {(cuuint64_t)K, (cuuint64_t)rows, 1};
    cuuint64_t str[2] = {(cuuint64_t)K * 2, (cuuint64_t)K * (cuuint64_t)rows * 2};
    cuuint32_t box[3] = {32, 128, 1};
    cuuint32_t es[3] = {1, 1, 1};
    fn(m, CU_TENSOR_MAP_DATA_TYPE_BFLOAT16, 3, (void*)p, dims, str, box, es,
       CU_TENSOR_MAP_INTERLEAVE_NONE, CU_TENSOR_MAP_SWIZZLE_64B,
       CU_TENSOR_MAP_L2_PROMOTION_L2_128B, CU_TENSOR_MAP_FLOAT_OOB_FILL_NONE);
}

static void rung(PFN_enc fn, int epi,
                 const __nv_bfloat16* Ah, const __nv_bfloat16* Al,
                 const __nv_bfloat16* Bh, const __nv_bfloat16* Bl,
                 float* Cf, __nv_bfloat16* Ch, __nv_bfloat16* Cl,
                 const float* OTH, int M, int N, int K)
{
    CUtensorMap ma, mal, mb, mbl;
    enc_map(fn, &ma, Ah, K, M);  enc_map(fn, &mal, Al, K, M);
    enc_map(fn, &mb, Bh, K, N);  enc_map(fn, &mbl, Bl, K, N);
    const dim3 g(N / 128, M / 128), b(256);
    if (epi == 0) {
        cudaFuncSetAttribute(gemm_b3<0>, cudaFuncAttributeMaxDynamicSharedMemorySize, SMEM_TOT);
        gemm_b3<0><<<g, b, SMEM_TOT>>>(ma, mal, mb, mbl, Cf, Ch, Cl, OTH, M, N, K);
    } else if (epi == 1) {
        cudaFuncSetAttribute(gemm_b3<1>, cudaFuncAttributeMaxDynamicSharedMemorySize, SMEM_TOT);
        gemm_b3<1><<<g, b, SMEM_TOT>>>(ma, mal, mb, mbl, Cf, Ch, Cl, OTH, M, N, K);
    } else {
        cudaFuncSetAttribute(gemm_b3<2>, cudaFuncAttributeMaxDynamicSharedMemorySize, SMEM_TOT);
        gemm_b3<2><<<g, b, SMEM_TOT>>>(ma, mal, mb, mbl, Cf, Ch, Cl, OTH, M, N, K);
    }
}

extern "C" void kernel_launch(void* const* d_in, const int* in_sizes, int n_in,
                              void* d_out, int out_size)
{
    const float* x  = (const float*)d_in[0];
    const float* wu = (const float*)d_in[1];
    const float* wg = (const float*)d_in[2];
    const float* wd = (const float*)d_in[3];
    const float* h1 = (const float*)d_in[4];
    const float* h2 = (const float*)d_in[5];
    const float* h3 = (const float*)d_in[6];

    int F = 1;
    while ((long long)(F + 1) * (F + 1) <= (long long)in_sizes[4]) F++;
    const int D = in_sizes[1] / F;
    const int M = in_sizes[0] / D;

    __nv_bfloat16* bb;
    float* C1;
    cudaGetSymbolAddress((void**)&bb, g_bf);
    cudaGetSymbolAddress((void**)&C1, g_c1);

    __nv_bfloat16 *xh = bb,            *xl = bb + MDE;
    __nv_bfloat16 *wuh = bb + 2 * MDE, *wul = bb + 3 * MDE;
    __nv_bfloat16 *wgh = bb + 4 * MDE, *wgl = bb + 5 * MDE;
    __nv_bfloat16 *wdh = bb + 6 * MDE, *wdl = bb + 7 * MDE;
    __nv_bfloat16* hb = bb + 8 * MDE;
    __nv_bfloat16 *h1h = hb,           *h1l = hb + FFE;
    __nv_bfloat16 *h2h = hb + 2 * FFE, *h2l = hb + 3 * FFE;
    __nv_bfloat16 *h3h = hb + 4 * FFE, *h3l = hb + 5 * FFE;
    __nv_bfloat16 *Uh = hb + 6 * FFE,  *Ul = hb + 7 * FFE;
    __nv_bfloat16 *Gh = hb + 8 * FFE,  *Gl = hb + 9 * FFE;

    const int nMD4 = (M * D) / 4, nFD4 = (F * D) / 4;
    split_k<<<2048, 256>>>((const float4*)x,  (bf4*)xh,  (bf4*)xl,  nMD4);
    split_k<<<2048, 256>>>((const float4*)wu, (bf4*)wuh, (bf4*)wul, nFD4);
    split_k<<<2048, 256>>>((const float4*)wg, (bf4*)wgh, (bf4*)wgl, nFD4);
    split_k<<<2048, 256>>>((const float4*)wd, (bf4*)wdh, (bf4*)wdl, nFD4);
    const dim3 tg(F / 32, F / 32), tb(32, 8);
    tsplit_k<<<tg, tb>>>(h1, h1h, h1l, F);
    tsplit_k<<<tg, tb>>>(h2, h2h, h2l, F);
    tsplit_k<<<tg, tb>>>(h3, h3h, h3l, F);

    PFN_enc fn = nullptr;
    cudaDriverEntryPointQueryResult qr;
    cudaGetDriverEntryPoint("cuTensorMapEncodeTiled", (void**)&fn, cudaEnableDefault, &qr);

    // 1) up   = x @ w_up^T            -> split U
    rung(fn, 0, xh, xl, wuh, wul, nullptr, Uh, Ul, nullptr, M, F, D);
    // 2) gate = x @ w_gate^T          -> split G
    rung(fn, 0, xh, xl, wgh, wgl, nullptr, Gh, Gl, nullptr, M, F, D);
    // 3) up2  = U @ h_up_T            -> C1 (fp32)
    rung(fn, 1, Uh, Ul, h1h, h1l, C1, nullptr, nullptr, nullptr, M, F, F);
    // 4) gated = C1 * silu(G @ h_gate_T) -> split U (reuse)
    rung(fn, 2, Gh, Gl, h2h, h2l, nullptr, Uh, Ul, C1, M, F, F);
    // 5) g3   = gated @ h_down        -> split G (reuse)
    rung(fn, 0, Uh, Ul, h3h, h3l, nullptr, Gh, Gl, nullptr, M, F, F);
    // 6) out  = g3 @ w_down^T         -> d_out (fp32)
    rung(fn, 1, Gh, Gl, wdh, wdl, (float*)d_out, nullptr, nullptr, nullptr, M, D, F);
}

// round 8
// speedup vs baseline: 3.0326x; 2.3619x over previous
#include <cuda_runtime.h>
#include <cuda.h>
#include <cuda_bf16.h>
#include <math.h>
#include <stdint.h>

// ===========================================================================
// R7: Hadamard-fold refactor. out = x@(wu^T h1) etc. — 2.5x fewer MACs.
// GEMM engine unchanged from R6: bf16x3 split mma.sync + TMA (SWIZZLE_64B),
// 128x128x32 tile, 2 CTA/SM, 3-stage mbarrier ring.
// ===========================================================================

#define TILE_B 8192              // one 128x32 bf16 tile in smem (bytes)
#define STAGE_B 32768            // 4 tiles (Ah,Al,Bh,Bl)
#define SMEM_TOT (1024 + 1024 + 3 * STAGE_B)

__device__ __forceinline__ uint32_t smem_u32(const void* p) {
    uint32_t a;
    asm("{ .reg .u64 t; cvta.to.shared.u64 t, %1; cvt.u32.u64 %0, t; }" : "=r"(a) : "l"(p));
    return a;
}
#define MBARRIER_INIT(a, c) \
    asm volatile("mbarrier.init.shared.b64 [%0], %1;" :: "r"((uint32_t)(a)), "r"((uint32_t)(c)) : "memory")
#define MBARRIER_EXPECT_TX(a, b) \
    asm volatile("mbarrier.arrive.expect_tx.shared.b64 _, [%0], %1;" :: "r"((uint32_t)(a)), "r"((uint32_t)(b)) : "memory")
#define MBARRIER_WAIT_PARITY(a, p) do { \
    uint32_t _m = (uint32_t)(a), _p = (uint32_t)(p), _d; \
    asm volatile("{\n\t.reg .pred q;\n\t" \
        "mbarrier.try_wait.parity.acquire.cta.shared::cta.b64 q, [%1], %2;\n\t" \
        "selp.b32 %0, 1, 0, q;\n\t}" : "=r"(_d) : "r"(_m), "r"(_p) : "memory"); \
    if (!_d) { \
        asm volatile("{\n\t.reg .pred Q;\n\t" \
            "WL_%=:\n\t" \
            "mbarrier.try_wait.parity.acquire.cta.shared::cta.b64 Q, [%0], %1, 0x989680;\n\t" \
            "@Q bra.uni WD_%=;\n\t" \
            "bra.uni WL_%=;\n\t" \
            "WD_%=:\n\t}" :: "r"(_m), "r"(_p) : "memory"); \
    } \
} while (0)
#define TMA_LOAD_3D(sa, tm, cx, cy, cz, mb) \
    asm volatile("cp.async.bulk.tensor.3d.shared::cta.global.tile.mbarrier::complete_tx::bytes " \
        "[%0], [%1, {%2, %3, %4}], [%5];" \
        :: "r"((uint32_t)(sa)), "l"(tm), "r"((int32_t)(cx)), "r"((int32_t)(cy)), \
           "r"((int32_t)(cz)), "r"((uint32_t)(mb)) : "memory")
#define LDSM4(R, a) \
    asm volatile("ldmatrix.sync.aligned.m8n8.x4.shared.b16 {%0,%1,%2,%3}, [%4];" \
        : "=r"((R)[0]), "=r"((R)[1]), "=r"((R)[2]), "=r"((R)[3]) : "r"(a))

__device__ __forceinline__ void mma_bf16(float* c, const uint32_t* a, uint32_t b0, uint32_t b1) {
    asm volatile(
        "mma.sync.aligned.m16n8k16.row.col.f32.bf16.bf16.f32 "
        "{%0,%1,%2,%3}, {%4,%5,%6,%7}, {%8,%9}, {%0,%1,%2,%3};"
        : "+f"(c[0]), "+f"(c[1]), "+f"(c[2]), "+f"(c[3])
        : "r"(a[0]), "r"(a[1]), "r"(a[2]), "r"(a[3]), "r"(b0), "r"(b1));
}

// 16B-granular XOR swizzle within a [rows x 32] bf16 tile (64B rows).
// Identical to TMA CU_TENSOR_MAP_SWIZZLE_64B layout for 64B-wide boxes.
__device__ __forceinline__ uint32_t sw(int row, int col16) {
    return (uint32_t)(row * 64 + ((col16 ^ ((row >> 1) & 3)) << 4));
}

// EPI 0: split-write (Ch,Cl bf16).  EPI 1: fp32 write Cf.
// EPI 2: v = OTH * silu(acc), split-write.
template <int EPI>
__global__ __launch_bounds__(256, 2) void gemm_b3(
    const __grid_constant__ CUtensorMap tAh, const __grid_constant__ CUtensorMap tAl,
    const __grid_constant__ CUtensorMap tBh, const __grid_constant__ CUtensorMap tBl,
    float* __restrict__ Cf, __nv_bfloat16* __restrict__ Ch, __nv_bfloat16* __restrict__ Cl,
    const float* __restrict__ OTH, int M, int N, int K)
{
    extern __shared__ char smem[];
    const uint32_t sb0 = smem_u32(smem);
    const uint32_t sb = (sb0 + 1023) & ~1023u;   // 1KB-align for TMA swizzle
    const int tid = threadIdx.x;

    // ---- L2-friendly CTA rasterization (GROUP_M = 16) ----
    const int gn = gridDim.x, gm = gridDim.y;
    const int bid = blockIdx.y * gn + blockIdx.x;
    const int npg = 16 * gn;
    const int gid = bid / npg;
    const int fm = gid * 16;
    const int gs = (gm - fm < 16) ? (gm - fm) : 16;
    const int bm = (fm + (bid % gs)) * 128;
    const int bn = ((bid % npg) / gs) * 128;

    const int w = tid >> 5, lane = tid & 31;
    const int wm = (w >> 2) * 64, wn = (w & 3) * 32;
    const int jj = lane >> 3, rr = lane & 7;
    const int aR = (jj & 1) * 8 + rr, aC16 = jj >> 1;   // A: (m0k0)(m8k0)(m0k8)(m8k8)
    const int bR = (jj >> 1) * 8 + rr, bC16 = jj & 1;   // B: (n0k0)(n0k8)(n8k0)(n8k8)

    const uint32_t bars = sb;                 // 3 x 8B mbarriers
    const uint32_t stg0 = sb + 1024;          // 3 x 32KB stages

    if (tid == 0) {
        MBARRIER_INIT(bars + 0, 1);
        MBARRIER_INIT(bars + 8, 1);
        MBARRIER_INIT(bars + 16, 1);
    }
    __syncthreads();

    const int nst = K / 32;

    // prologue: issue stages 0..2
    if (tid == 0) {
#pragma unroll
        for (int s = 0; s < 3; s++) {
            const uint32_t bar = bars + s * 8;
            const uint32_t stb = stg0 + s * STAGE_B;
            const int k0 = s * 32;
            MBARRIER_EXPECT_TX(bar, STAGE_B);
            TMA_LOAD_3D(stb,              &tAh, k0, bm, 0, bar);
            TMA_LOAD_3D(stb + TILE_B,     &tAl, k0, bm, 0, bar);
            TMA_LOAD_3D(stb + 2 * TILE_B, &tBh, k0, bn, 0, bar);
            TMA_LOAD_3D(stb + 3 * TILE_B, &tBl, k0, bn, 0, bar);
        }
    }

    float c[4][4][4];
#pragma unroll
    for (int mi = 0; mi < 4; mi++)
#pragma unroll
        for (int ni = 0; ni < 4; ni++)
#pragma unroll
            for (int q = 0; q < 4; q++) c[mi][ni][q] = 0.0f;

    for (int t = 0; t < nst; t++) {
        const int buf = t % 3;
        MBARRIER_WAIT_PARITY(bars + buf * 8, (t / 3) & 1);

        const uint32_t stb = stg0 + (uint32_t)buf * STAGE_B;
#pragma unroll
        for (int ks = 0; ks < 2; ks++) {
            uint32_t af[4][4], bhf[2][4], blf[2][4];
            // A-hi frags
#pragma unroll
            for (int mi = 0; mi < 4; mi++)
                LDSM4(af[mi], stb + sw(wm + mi * 16 + aR, ks * 2 + aC16));
            // B-hi / B-lo frags
#pragma unroll
            for (int np = 0; np < 2; np++) {
                const uint32_t bd = stb + 2 * TILE_B + sw(wn + np * 16 + bR, ks * 2 + bC16);
                LDSM4(bhf[np], bd);
                LDSM4(blf[np], bd + TILE_B);
            }
            // hh + hl
#pragma unroll
            for (int mi = 0; mi < 4; mi++)
#pragma unroll
                for (int ni = 0; ni < 4; ni++) {
                    const int p = ni >> 1, q = (ni & 1) * 2;
                    mma_bf16(c[mi][ni], af[mi], bhf[p][q], bhf[p][q + 1]);
                    mma_bf16(c[mi][ni], af[mi], blf[p][q], blf[p][q + 1]);
                }
            // A-lo frags overwrite A-hi (reduced liveness)
#pragma unroll
            for (int mi = 0; mi < 4; mi++)
                LDSM4(af[mi], stb + TILE_B + sw(wm + mi * 16 + aR, ks * 2 + aC16));
            // lh
#pragma unroll
            for (int mi = 0; mi < 4; mi++)
#pragma unroll
                for (int ni = 0; ni < 4; ni++) {
                    const int p = ni >> 1, q = (ni & 1) * 2;
                    mma_bf16(c[mi][ni], af[mi], bhf[p][q], bhf[p][q + 1]);
                }
        }

        __syncthreads();   // all warps done reading buf before refill
        if (t + 3 < nst && tid == 0) {
            const uint32_t bar = bars + buf * 8;
            const int k0 = (t + 3) * 32;
            MBARRIER_EXPECT_TX(bar, STAGE_B);
            TMA_LOAD_3D(stb,              &tAh, k0, bm, 0, bar);
            TMA_LOAD_3D(stb + TILE_B,     &tAl, k0, bm, 0, bar);
            TMA_LOAD_3D(stb + 2 * TILE_B, &tBh, k0, bn, 0, bar);
            TMA_LOAD_3D(stb + 3 * TILE_B, &tBl, k0, bn, 0, bar);
        }
    }

    // ---- epilogue ----
#pragma unroll
    for (int mi = 0; mi < 4; mi++)
#pragma unroll
        for (int ni = 0; ni < 4; ni++) {
            const int r0 = bm + wm + mi * 16 + (lane >> 2);
            const int col = bn + wn + ni * 8 + (lane & 3) * 2;
            const size_t o0 = (size_t)r0 * N + col;
            const size_t o1 = (size_t)(r0 + 8) * N + col;
            float v0 = c[mi][ni][0], v1 = c[mi][ni][1];
            float v2 = c[mi][ni][2], v3 = c[mi][ni][3];
            if (EPI == 2) {
                const float2 u0 = *(const float2*)(OTH + o0);
                const float2 u1 = *(const float2*)(OTH + o1);
                v0 = u0.x * (v0 / (1.0f + expf(-v0)));
                v1 = u0.y * (v1 / (1.0f + expf(-v1)));
                v2 = u1.x * (v2 / (1.0f + expf(-v2)));
                v3 = u1.y * (v3 / (1.0f + expf(-v3)));
            }
            if (EPI == 1) {
                *(float2*)(Cf + o0) = make_float2(v0, v1);
                *(float2*)(Cf + o1) = make_float2(v2, v3);
            } else {
                __nv_bfloat162 hh, ll;
                hh.x = __float2bfloat16(v0); hh.y = __float2bfloat16(v1);
                ll.x = __float2bfloat16(v0 - __bfloat162float(hh.x));
                ll.y = __float2bfloat16(v1 - __bfloat162float(hh.y));
                *(__nv_bfloat162*)(Ch + o0) = hh;
                *(__nv_bfloat162*)(Cl + o0) = ll;
                hh.x = __float2bfloat16(v2); hh.y = __float2bfloat16(v3);
                ll.x = __float2bfloat16(v2 - __bfloat162float(hh.x));
                ll.y = __float2bfloat16(v3 - __bfloat162float(hh.y));
                *(__nv_bfloat162*)(Ch + o1) = hh;
                *(__nv_bfloat162*)(Cl + o1) = ll;
            }
        }
}

// ===========================================================================
// scratch (static; no allocations).
// ===========================================================================
#define MDE 16777216ll
#define FFE 67108864ll
__device__ __nv_bfloat16 g_bf[805306368];
__device__ float g_c1[67108864];

// ---- pre-pass: fp32 -> (bf16 hi, bf16 lo) ----
struct bf4 { __nv_bfloat162 a, b; };
__global__ void split_k(const float4* __restrict__ in, bf4* __restrict__ hi,
                        bf4* __restrict__ lo, int n4) {
    for (int i = blockIdx.x * blockDim.x + threadIdx.x; i < n4; i += gridDim.x * blockDim.x) {
        const float4 v = in[i];
        bf4 H, L;
        H.a.x = __float2bfloat16(v.x); H.a.y = __float2bfloat16(v.y);
        H.b.x = __float2bfloat16(v.z); H.b.y = __float2bfloat16(v.w);
        L.a.x = __float2bfloat16(v.x - __bfloat162float(H.a.x));
        L.a.y = __float2bfloat16(v.y - __bfloat162float(H.a.y));
        L.b.x = __float2bfloat16(v.z - __bfloat162float(H.b.x));
        L.b.y = __float2bfloat16(v.w - __bfloat162float(H.b.y));
        hi[i] = H; lo[i] = L;
    }
}
// rectangular transpose + split: in [R,C] -> out_{hi,lo} [C,R]
__global__ void tsplit_k(const float* __restrict__ in, __nv_bfloat16* __restrict__ hi,
                         __nv_bfloat16* __restrict__ lo, int R, int C) {
    __shared__ float t[32][33];
    const int c0 = blockIdx.x * 32, r0 = blockIdx.y * 32;
#pragma unroll
    for (int i = 0; i < 32; i += 8)
        t[threadIdx.y + i][threadIdx.x] = in[(size_t)(r0 + threadIdx.y + i) * C + c0 + threadIdx.x];
    __syncthreads();
#pragma unroll
    for (int i = 0; i < 32; i += 8) {
        const float v = t[threadIdx.x][threadIdx.y + i];
        const __nv_bfloat16 h = __float2bfloat16(v);
        const size_t o = (size_t)(c0 + threadIdx.y + i) * R + r0 + threadIdx.x;
        hi[o] = h;
        lo[o] = __float2bfloat16(v - __bfloat162float(h));
    }
}

// ===========================================================================
typedef CUresult (*PFN_enc)(CUtensorMap*, CUtensorMapDataType, cuuint32_t, void*,
                            const cuuint64_t*, const cuuint64_t*, const cuuint32_t*,
                            const cuuint32_t*, CUtensorMapInterleave, CUtensorMapSwizzle,
                            CUtensorMapL2promotion, CUtensorMapFloatOOBfill);

static void enc_map(PFN_enc fn, CUtensorMap* m, const __nv_bfloat16* p, int K, int rows) {
    cuuint64_t dims[3] = {(cuuint64_t)K, (cuuint64_t)rows, 1};
    cuuint64_t str[2] = {(cuuint64_t)K * 2, (cuuint64_t)K * (cuuint64_t)rows * 2};
    cuuint32_t box[3] = {32, 128, 1};
    cuuint32_t es[3] = {1, 1, 1};
    fn(m, CU_TENSOR_MAP_DATA_TYPE_BFLOAT16, 3, (void*)p, dims, str, box, es,
       CU_TENSOR_MAP_INTERLEAVE_NONE, CU_TENSOR_MAP_SWIZZLE_64B,
       CU_TENSOR_MAP_L2_PROMOTION_L2_128B, CU_TENSOR_MAP_FLOAT_OOB_FILL_NONE);
}

static void rung(PFN_enc fn, int epi,
                 const __nv_bfloat16* Ah, const __nv_bfloat16* Al,
                 const __nv_bfloat16* Bh, const __nv_bfloat16* Bl,
                 float* Cf, __nv_bfloat16* Ch, __nv_bfloat16* Cl,
                 const float* OTH, int M, int N, int K)
{
    CUtensorMap ma, mal, mb, mbl;
    enc_map(fn, &ma, Ah, K, M);  enc_map(fn, &mal, Al, K, M);
    enc_map(fn, &mb, Bh, K, N);  enc_map(fn, &mbl, Bl, K, N);
    const dim3 g(N / 128, M / 128), b(256);
    if (epi == 0) {
        cudaFuncSetAttribute(gemm_b3<0>, cudaFuncAttributeMaxDynamicSharedMemorySize, SMEM_TOT);
        gemm_b3<0><<<g, b, SMEM_TOT>>>(ma, mal, mb, mbl, Cf, Ch, Cl, OTH, M, N, K);
    } else if (epi == 1) {
        cudaFuncSetAttribute(gemm_b3<1>, cudaFuncAttributeMaxDynamicSharedMemorySize, SMEM_TOT);
        gemm_b3<1><<<g, b, SMEM_TOT>>>(ma, mal, mb, mbl, Cf, Ch, Cl, OTH, M, N, K);
    } else {
        cudaFuncSetAttribute(gemm_b3<2>, cudaFuncAttributeMaxDynamicSharedMemorySize, SMEM_TOT);
        gemm_b3<2><<<g, b, SMEM_TOT>>>(ma, mal, mb, mbl, Cf, Ch, Cl, OTH, M, N, K);
    }
}

extern "C" void kernel_launch(void* const* d_in, const int* in_sizes, int n_in,
                              void* d_out, int out_size)
{
    const float* x  = (const float*)d_in[0];
    const float* wu = (const float*)d_in[1];
    const float* wg = (const float*)d_in[2];
    const float* wd = (const float*)d_in[3];
    const float* h1 = (const float*)d_in[4];   // h_up_T   [F,F]
    const float* h2 = (const float*)d_in[5];   // h_gate_T [F,F]
    const float* h3 = (const float*)d_in[6];   // h_down   [F,F]

    int F = 1;
    while ((long long)(F + 1) * (F + 1) <= (long long)in_sizes[4]) F++;
    const int D = in_sizes[1] / F;
    const int M = in_sizes[0] / D;

    __nv_bfloat16* bb;
    float* C1;
    cudaGetSymbolAddress((void**)&bb, g_bf);
    cudaGetSymbolAddress((void**)&C1, g_c1);

    // slab layout: 14 MD-blocks + 8 FF-blocks = 771.8M elems <= 805.3M
    __nv_bfloat16 *xh   = bb,            *xl   = bb + MDE;
    __nv_bfloat16 *wuth = bb + 2 * MDE,  *wutl = bb + 3 * MDE;   // w_up^T   [D,F]
    __nv_bfloat16 *wgth = bb + 4 * MDE,  *wgtl = bb + 5 * MDE;   // w_gate^T [D,F]
    __nv_bfloat16 *wdh  = bb + 6 * MDE,  *wdl  = bb + 7 * MDE;   // w_down   [D,F]
    __nv_bfloat16 *V1h  = bb + 8 * MDE,  *V1l  = bb + 9 * MDE;   // [F,D]
    __nv_bfloat16 *V2h  = bb + 10 * MDE, *V2l  = bb + 11 * MDE;  // [F,D]
    __nv_bfloat16 *V3h  = bb + 12 * MDE, *V3l  = bb + 13 * MDE;  // [D,F]
    __nv_bfloat16* hb = bb + 14 * MDE;
    __nv_bfloat16 *h1th = hb,            *h1tl = hb + FFE;       // h_up_T^T   [F,F]
    __nv_bfloat16 *h2th = hb + 2 * FFE,  *h2tl = hb + 3 * FFE;   // h_gate_T^T [F,F]
    __nv_bfloat16 *hdh  = hb + 4 * FFE,  *hdl  = hb + 5 * FFE;   // h_down     [F,F]
    __nv_bfloat16 *Uh   = hb + 6 * FFE,  *Ul   = hb + 7 * FFE;   // gated      [M,F]

    // ---- prepass: splits & transpose-splits ----
    split_k<<<2048, 256>>>((const float4*)x,  (bf4*)xh,  (bf4*)xl,  (M * D) / 4);
    split_k<<<2048, 256>>>((const float4*)wd, (bf4*)wdh, (bf4*)wdl, (D * F) / 4);
    split_k<<<2048, 256>>>((const float4*)h3, (bf4*)hdh, (bf4*)hdl, (F * F) / 4);
    const dim3 tb(32, 8);
    tsplit_k<<<dim3(F / 32, F / 32), tb>>>(h1, h1th, h1tl, F, F);   // [F,F] -> [F,F]
    tsplit_k<<<dim3(F / 32, F / 32), tb>>>(h2, h2th, h2tl, F, F);
    tsplit_k<<<dim3(D / 32, F / 32), tb>>>(wu, wuth, wutl, F, D);   // [F,D] -> [D,F]
    tsplit_k<<<dim3(D / 32, F / 32), tb>>>(wg, wgth, wgtl, F, D);

    PFN_enc fn = nullptr;
    cudaDriverEntryPointQueryResult qr;
    cudaGetDriverEntryPoint("cuTensorMapEncodeTiled", (void**)&fn, cudaEnableDefault, &qr);

    // ---- weight-fold GEMMs (M-independent, 137G each) ----
    // V1[f,d] = sum_f' h_up_T[f',f] * w_up[f',d]   (A=h1t [F,F'], B=wut [D,F'])
    rung(fn, 0, h1th, h1tl, wuth, wutl, nullptr, V1h, V1l, nullptr, F, D, F);
    // V2[f,d] analogous for the gate branch
    rung(fn, 0, h2th, h2tl, wgth, wgtl, nullptr, V2h, V2l, nullptr, F, D, F);
    // V3[d,f] = sum_f2 w_down[d,f2] * h_down[f,f2]  (A=wd [D,F2], B=hd [F,F2])
    rung(fn, 0, wdh, wdl, hdh, hdl, nullptr, V3h, V3l, nullptr, D, F, F);

    // ---- activation GEMMs (137G each) ----
    // up2 = x @ V1^T -> C1 (fp32)
    rung(fn, 1, xh, xl, V1h, V1l, C1, nullptr, nullptr, nullptr, M, F, D);
    // gated = C1 * silu(x @ V2^T) -> split U
    rung(fn, 2, xh, xl, V2h, V2l, nullptr, Uh, Ul, C1, M, F, D);
    // out = gated @ V3^T -> d_out (fp32)
    rung(fn, 1, Uh, Ul, V3h, V3l, (float*)d_out, nullptr, nullptr, nullptr, M, D, F);
}